// round 16
// baseline (speedup 1.0000x reference)
#include <cuda_runtime.h>
#include <cstdint>

#define BATCH 8
#define MDIM  2048
#define LDIM  2048
#define HDIM  1024
#define BK    8
#define NTHREADS 256

// Scratch: T = K^T V, [B,H,H] fp32 (module-load allocated; allocs forbidden)
__device__ float g_T[(size_t)BATCH * HDIM * HDIM];

// ---------------------------------------------------------------------------
// Both kernels: 128x128 tile, BK=8, 256 threads, 8x8 microtile.
// Fragments: rows ty*8 (broadcast), cols tx*4 & 64+tx*4 (conflict-free).
// Double-buffered smem + register prefetch across compute:
//   per iter:  STS(c) -> sync -> LDG(c+1) -> compute(c)
// Prefetch = 2 float4 (8 floats) live across compute -- fits the 128-reg cap
// (16+ live floats spilled in R8/R9; cp.async measured pathological).
// ---------------------------------------------------------------------------

// Kernel 1: T[i][j] = sum_l K[l][i] * V[l][j]   (both operands k-major)
__global__ __launch_bounds__(NTHREADS, 2) void ktv_kernel(
    const float* __restrict__ Kp, const float* __restrict__ Vp)
{
    const int b = blockIdx.z;
    const float* A = Kp + (size_t)b * LDIM * HDIM;  // [L,H] rows l
    const float* B = Vp + (size_t)b * LDIM * HDIM;  // [L,H] rows l
    float* C = g_T + (size_t)b * HDIM * HDIM;       // [H,H]

    __shared__ float As[2][BK][128];
    __shared__ float Bs[2][BK][128];

    const int tid = threadIdx.x;
    const int ty = tid >> 4, tx = tid & 15;
    const int m0 = blockIdx.y * 128, n0 = blockIdx.x * 128;

    const int kr = tid >> 5;             // 0..7
    const int c4 = (tid & 31) << 2;      // 0..124

    float acc[8][8];
#pragma unroll
    for (int i = 0; i < 8; i++)
#pragma unroll
        for (int j = 0; j < 8; j++) acc[i][j] = 0.0f;

    const int NK = LDIM / BK;

    float4 pa = *(const float4*)(A + (size_t)kr * HDIM + m0 + c4);
    float4 pb = *(const float4*)(B + (size_t)kr * HDIM + n0 + c4);

    for (int c = 0; c < NK; c++) {
        const int buf = c & 1;
        *(float4*)&As[buf][kr][c4] = pa;
        *(float4*)&Bs[buf][kr][c4] = pb;
        __syncthreads();

        if (c + 1 < NK) {
            const int l0 = (c + 1) * BK;
            pa = *(const float4*)(A + (size_t)(l0 + kr) * HDIM + m0 + c4);
            pb = *(const float4*)(B + (size_t)(l0 + kr) * HDIM + n0 + c4);
        }

#pragma unroll
        for (int k = 0; k < BK; k++) {
            float4 a0 = *(const float4*)&As[buf][k][ty * 8];
            float4 a1 = *(const float4*)&As[buf][k][ty * 8 + 4];
            float4 b0 = *(const float4*)&Bs[buf][k][tx * 4];
            float4 b1 = *(const float4*)&Bs[buf][k][64 + tx * 4];
            const float av[8] = {a0.x, a0.y, a0.z, a0.w, a1.x, a1.y, a1.z, a1.w};
            const float bv[8] = {b0.x, b0.y, b0.z, b0.w, b1.x, b1.y, b1.z, b1.w};
#pragma unroll
            for (int i = 0; i < 8; i++)
#pragma unroll
                for (int j = 0; j < 8; j++)
                    acc[i][j] = fmaf(av[i], bv[j], acc[i][j]);
        }
    }

#pragma unroll
    for (int i = 0; i < 8; i++) {
        float* crow = C + (size_t)(m0 + ty * 8 + i) * HDIM + n0;
        *reinterpret_cast<float4*>(crow + tx * 4) =
            make_float4(acc[i][0], acc[i][1], acc[i][2], acc[i][3]);
        *reinterpret_cast<float4*>(crow + 64 + tx * 4) =
            make_float4(acc[i][4], acc[i][5], acc[i][6], acc[i][7]);
    }
}

// Kernel 2: O[m][j] = sum_h Q[m][h] * T[h][j]
// A = Q [M,H] m-major -> transpose-on-STS; B = T [H,H] k-major direct.
__global__ __launch_bounds__(NTHREADS, 2) void qt_kernel(
    const float* __restrict__ Qp, float* __restrict__ Op)
{
    const int b = blockIdx.z;
    const float* A = Qp + (size_t)b * MDIM * HDIM;  // [M,H] rows m
    const float* B = g_T + (size_t)b * HDIM * HDIM; // [H,H] rows h
    float* C = Op + (size_t)b * MDIM * HDIM;        // [M,H]

    __shared__ float As[2][BK][128];
    __shared__ float Bs[2][BK][128];

    const int tid = threadIdx.x;
    const int ty = tid >> 4, tx = tid & 15;
    const int m0 = blockIdx.y * 128, n0 = blockIdx.x * 128;

    // A tile: 128 rows x 8 k = 256 float4, 1/thread: row tid>>1, k4 = (tid&1)*4
    const int am = tid >> 1;             // 0..127
    const int ak4 = (tid & 1) << 2;      // 0 or 4
    // B tile: 8 rows x 128 = 256 float4, 1/thread
    const int kr = tid >> 5;             // 0..7
    const int c4 = (tid & 31) << 2;      // 0..124

    float acc[8][8];
#pragma unroll
    for (int i = 0; i < 8; i++)
#pragma unroll
        for (int j = 0; j < 8; j++) acc[i][j] = 0.0f;

    const int NK = HDIM / BK;

    float4 pa = *(const float4*)(A + (size_t)(m0 + am) * HDIM + ak4);
    float4 pb = *(const float4*)(B + (size_t)kr * HDIM + n0 + c4);

    for (int c = 0; c < NK; c++) {
        const int buf = c & 1;
        As[buf][ak4 + 0][am] = pa.x;
        As[buf][ak4 + 1][am] = pa.y;
        As[buf][ak4 + 2][am] = pa.z;
        As[buf][ak4 + 3][am] = pa.w;
        *(float4*)&Bs[buf][kr][c4] = pb;
        __syncthreads();

        if (c + 1 < NK) {
            const int h0 = (c + 1) * BK;
            pa = *(const float4*)(A + (size_t)(m0 + am) * HDIM + h0 + ak4);
            pb = *(const float4*)(B + (size_t)(h0 + kr) * HDIM + n0 + c4);
        }

#pragma unroll
        for (int k = 0; k < BK; k++) {
            float4 a0 = *(const float4*)&As[buf][k][ty * 8];
            float4 a1 = *(const float4*)&As[buf][k][ty * 8 + 4];
            float4 b0 = *(const float4*)&Bs[buf][k][tx * 4];
            float4 b1 = *(const float4*)&Bs[buf][k][64 + tx * 4];
            const float av[8] = {a0.x, a0.y, a0.z, a0.w, a1.x, a1.y, a1.z, a1.w};
            const float bv[8] = {b0.x, b0.y, b0.z, b0.w, b1.x, b1.y, b1.z, b1.w};
#pragma unroll
            for (int i = 0; i < 8; i++)
#pragma unroll
                for (int j = 0; j < 8; j++)
                    acc[i][j] = fmaf(av[i], bv[j], acc[i][j]);
        }
    }

#pragma unroll
    for (int i = 0; i < 8; i++) {
        float* crow = C + (size_t)(m0 + ty * 8 + i) * HDIM + n0;
        *reinterpret_cast<float4*>(crow + tx * 4) =
            make_float4(acc[i][0], acc[i][1], acc[i][2], acc[i][3]);
        *reinterpret_cast<float4*>(crow + 64 + tx * 4) =
            make_float4(acc[i][4], acc[i][5], acc[i][6], acc[i][7]);
    }
}

// ---------------------------------------------------------------------------
// Launch: out = Q @ (K^T @ V). key_pe / hidden_size are dead inputs
// (attn_pos and the softmax are dead code in the reference).
// ---------------------------------------------------------------------------
extern "C" void kernel_launch(void* const* d_in, const int* in_sizes, int n_in,
                              void* d_out, int out_size)
{
    const float* q = (const float*)d_in[0];  // [B, M, H]
    const float* k = (const float*)d_in[1];  // [B, L, H]
    const float* v = (const float*)d_in[2];  // [B, L, H]
    float* out = (float*)d_out;              // [B, M, H]

    dim3 g1(HDIM / 128, HDIM / 128, BATCH);
    ktv_kernel<<<g1, NTHREADS>>>(k, v);

    dim3 g2(HDIM / 128, MDIM / 128, BATCH);
    qt_kernel<<<g2, NTHREADS>>>(q, out);
}